// round 10
// baseline (speedup 1.0000x reference)
#include <cuda_runtime.h>
#include <math.h>
#include <stdint.h>

#define BB 64
#define SS 196
#define EE 768
#define HH 4
#define HD 192
#define SP 224              /* padded seq (196 -> 224 = 7*32) */
#define GRID14 14
#define BSROWS (BB*SS)      /* 12544 */
#define SE (SS*EE)          /* 150528 */
#define LN_EPS 1e-5f

// ---------------- scratch (static device arrays; no cudaMalloc) -------------
__device__ float g_emb[BSROWS*EE];      // skip1
__device__ float g_h[BSROWS*EE];        // LN1 output
__device__ float g_q[BSROWS*EE];
__device__ float g_k[BSROWS*EE];
__device__ float g_v[BSROWS*EE];
__device__ float g_vt[BB*HH*HD*SP];     // V transposed per head, s padded
__device__ float g_scores[BB*HH*SP*SP]; // padded scores/probs
__device__ float g_attno[BSROWS*EE];
__device__ float g_res[BSROWS*EE];      // skip1 + proj (pre-LN2)
__device__ float g_part[BB*4*2];        // partial LN sums
__device__ float g_stats[BB*2];         // mean, rstd per batch

// =================== helpers ================================================
__device__ __forceinline__ uint32_t smem_u32(const void* p) {
    uint32_t a;
    asm("{ .reg .u64 t; cvta.to.shared.u64 t, %1; cvt.u32.u64 %0, t; }"
        : "=r"(a) : "l"(p));
    return a;
}

__device__ __forceinline__ void cp16(void* smem_dst, const void* gmem_src) {
    uint32_t s = smem_u32(smem_dst);
    asm volatile("cp.async.cg.shared.global [%0], [%1], 16;"
                 :: "r"(s), "l"(gmem_src) : "memory");
}
__device__ __forceinline__ void cp16z(void* smem_dst, const void* gmem_src, bool v) {
    uint32_t s = smem_u32(smem_dst);
    int sz = v ? 16 : 0;
    asm volatile("cp.async.cg.shared.global [%0], [%1], 16, %2;"
                 :: "r"(s), "l"(gmem_src), "r"(sz) : "memory");
}
#define CP_COMMIT() asm volatile("cp.async.commit_group;" ::: "memory")
#define CP_WAIT0()  asm volatile("cp.async.wait_group 0;" ::: "memory")

// mma.sync m16n8k8 tf32: D(16x8,f32) += A(16x8,tf32) * B(8x8,tf32)
__device__ __forceinline__ void mma_tf32(float* c, const uint32_t* a,
                                         const uint32_t* b) {
    asm volatile(
        "mma.sync.aligned.m16n8k8.row.col.f32.tf32.tf32.f32 "
        "{%0,%1,%2,%3}, {%4,%5,%6,%7}, {%8,%9}, {%0,%1,%2,%3};"
        : "+f"(c[0]), "+f"(c[1]), "+f"(c[2]), "+f"(c[3])
        : "r"(a[0]), "r"(a[1]), "r"(a[2]), "r"(a[3]), "r"(b[0]), "r"(b[1]));
}

// =================== shared constants =======================================
#define LDSD 40                       /* padded row stride; 40%32=8 */
// ---- big GEMM (128x256 CTA tile, 64x64 warp tile) ----
#define ATILEF (128 * LDSD)           /* 5120 floats */
#define BTILEF (256 * LDSD)           /* 10240 floats */
#define STAGEF (ATILEF + BTILEF)      /* 15360 floats */
#define BIG_SMEM_BYTES (2 * STAGEF * 4)   /* 122880 B */
// ---- attention GEMM (128x128 CTA tile, 64x32 warp tile) ----
#define TILEF (128 * LDSD)
#define ATT_SMEM_BYTES (4 * TILEF * 4)    /* 81920 B */

// k-permutation fragment loads (thread tg holds logical cols kk+2tg, kk+2tg+1)
// -- valid because the same permutation is applied to A and B fragments.

// =================== big tf32 GEMM: 128x256 tile ============================
// C[M,N] = A[M,K]*B[N,K]^T + bias (+skip). M%128==0, N%256==0, K%32==0.
// MODE 0: A row-major gmem.  MODE 1: A = patch-gather from image x.
__device__ __forceinline__ const float* embed_addr(const float* x, int m, int col) {
    int b = m / SS, s = m - b * SS;
    int gy = s / GRID14, gx = s - gy * GRID14;
    int ch = col >> 8, r = col & 255;
    int py = r >> 4, px = r & 15;
    return x + (((size_t)(b * 3 + ch) * 224 + (gy * 16 + py)) * 224 + gx * 16 + px);
}

template <int MODE, bool HAS_SKIP>
__device__ __forceinline__ void gemm_big_body(
    float* sm, const float* __restrict__ A, const float* __restrict__ Bm,
    const float* __restrict__ bias, const float* __restrict__ skip,
    float* __restrict__ C, int M, int N, int K, int m0, int n0) {
    const int tid = threadIdx.x;
    const int wid = tid >> 5, lane = tid & 31;
    const int wm = wid >> 2, wn = wid & 3;          // warp 64x64 tile
    const int gl = lane >> 2, tg = lane & 3;
    const int srow = tid >> 3, sc4 = tid & 7;

    float acc[4][8][4];
#pragma unroll
    for (int i = 0; i < 4; i++)
#pragma unroll
        for (int j = 0; j < 8; j++)
#pragma unroll
            for (int r = 0; r < 4; r++) acc[i][j][r] = 0.f;

    const int NC = K >> 5;

    auto stage = [&](int c, int buf) {
        float* ad = sm + buf * STAGEF;
        float* bd = ad + ATILEF;
        const int colbase = c * 32 + sc4 * 4;
#pragma unroll
        for (int i = 0; i < 4; i++) {               // A: 128 rows
            int row = srow + i * 32;
            const float* asrc;
            if (MODE == 1) asrc = embed_addr(A, m0 + row, colbase);
            else           asrc = A + (size_t)(m0 + row) * K + colbase;
            cp16(ad + row * LDSD + sc4 * 4, asrc);
        }
#pragma unroll
        for (int i = 0; i < 8; i++) {               // B: 256 rows
            int row = srow + i * 32;
            cp16(bd + row * LDSD + sc4 * 4, Bm + (size_t)(n0 + row) * K + colbase);
        }
    };

    stage(0, 0); CP_COMMIT();

    for (int c = 0; c < NC; c++) {
        CP_WAIT0();
        __syncthreads();
        if (c + 1 < NC) { stage(c + 1, (c + 1) & 1); CP_COMMIT(); }
        const float* As = sm + (c & 1) * STAGEF + (wm * 64) * LDSD;
        const float* Bs = sm + (c & 1) * STAGEF + ATILEF + (wn * 64) * LDSD;
#pragma unroll
        for (int kk = 0; kk < 32; kk += 8) {
            uint32_t af[4][4], bf[8][2];
#pragma unroll
            for (int mt = 0; mt < 4; mt++) {
                const float2 x0 = *(const float2*)(As + (mt * 16 + gl) * LDSD + kk + 2 * tg);
                const float2 x1 = *(const float2*)(As + (mt * 16 + gl + 8) * LDSD + kk + 2 * tg);
                af[mt][0] = __float_as_uint(x0.x);
                af[mt][2] = __float_as_uint(x0.y);
                af[mt][1] = __float_as_uint(x1.x);
                af[mt][3] = __float_as_uint(x1.y);
            }
#pragma unroll
            for (int nt = 0; nt < 8; nt++) {
                const float2 y = *(const float2*)(Bs + (nt * 8 + gl) * LDSD + kk + 2 * tg);
                bf[nt][0] = __float_as_uint(y.x);
                bf[nt][1] = __float_as_uint(y.y);
            }
#pragma unroll
            for (int mt = 0; mt < 4; mt++)
#pragma unroll
                for (int nt = 0; nt < 8; nt++)
                    mma_tf32(acc[mt][nt], af[mt], bf[nt]);
        }
    }

#pragma unroll
    for (int mt = 0; mt < 4; mt++) {
        const int r0 = m0 + wm * 64 + mt * 16 + gl;
#pragma unroll
        for (int nt = 0; nt < 8; nt++) {
            const int col = n0 + wn * 64 + nt * 8 + tg * 2;
            const float2 bv = *(const float2*)(bias + col);
            float2 v0, v1;
            v0.x = acc[mt][nt][0] + bv.x;
            v0.y = acc[mt][nt][1] + bv.y;
            v1.x = acc[mt][nt][2] + bv.x;
            v1.y = acc[mt][nt][3] + bv.y;
            if (HAS_SKIP) {
                const float2 s0 = *(const float2*)(skip + (size_t)r0 * N + col);
                const float2 s1 = *(const float2*)(skip + (size_t)(r0 + 8) * N + col);
                v0.x += s0.x; v0.y += s0.y;
                v1.x += s1.x; v1.y += s1.y;
            }
            *(float2*)(C + (size_t)r0 * N + col)       = v0;
            *(float2*)(C + (size_t)(r0 + 8) * N + col) = v1;
        }
    }
}

__global__ __launch_bounds__(256, 1)
void gemm_embed(const float* __restrict__ x, const float* __restrict__ Bm,
                const float* __restrict__ bias, float* __restrict__ C) {
    extern __shared__ float sm[];
    gemm_big_body<1, false>(sm, x, Bm, bias, nullptr, C, BSROWS, EE, EE,
                            blockIdx.y * 128, blockIdx.x * 256);
}

__global__ __launch_bounds__(256, 1)
void gemm_qkv(const float* __restrict__ h,
              const float* __restrict__ wq, const float* __restrict__ wk,
              const float* __restrict__ wv, const float* __restrict__ bq,
              const float* __restrict__ bk, const float* __restrict__ bv,
              float* __restrict__ q, float* __restrict__ k, float* __restrict__ v) {
    extern __shared__ float sm[];
    const int z = blockIdx.z;
    const float* w = (z == 0) ? wq : (z == 1) ? wk : wv;
    const float* b = (z == 0) ? bq : (z == 1) ? bk : bv;
    float* o       = (z == 0) ? q  : (z == 1) ? k  : v;
    gemm_big_body<0, false>(sm, h, w, b, nullptr, o, BSROWS, EE, EE,
                            blockIdx.y * 128, blockIdx.x * 256);
}

__global__ __launch_bounds__(256, 1)
void gemm_proj(const float* __restrict__ a, const float* __restrict__ w,
               const float* __restrict__ bias, const float* __restrict__ skip,
               float* __restrict__ C) {
    extern __shared__ float sm[];
    gemm_big_body<0, true>(sm, a, w, bias, skip, C, BSROWS, EE, EE,
                           blockIdx.y * 128, blockIdx.x * 256);
}

// =================== attention 128x128 tile compute macro ===================
#define MMA_CHUNK_COMPUTE(As, Bs)                                             \
    do {                                                                      \
        _Pragma("unroll")                                                     \
        for (int kk = 0; kk < 32; kk += 8) {                                  \
            uint32_t af[4][4], bf[4][2];                                      \
            _Pragma("unroll")                                                 \
            for (int mt = 0; mt < 4; mt++) {                                  \
                const float2 x0 = *(const float2*)((As) + (mt * 16 + gl) * LDSD + kk + 2 * tg); \
                const float2 x1 = *(const float2*)((As) + (mt * 16 + gl + 8) * LDSD + kk + 2 * tg); \
                af[mt][0] = __float_as_uint(x0.x);                            \
                af[mt][2] = __float_as_uint(x0.y);                            \
                af[mt][1] = __float_as_uint(x1.x);                            \
                af[mt][3] = __float_as_uint(x1.y);                            \
            }                                                                 \
            _Pragma("unroll")                                                 \
            for (int nt = 0; nt < 4; nt++) {                                  \
                const float2 y = *(const float2*)((Bs) + (nt * 8 + gl) * LDSD + kk + 2 * tg); \
                bf[nt][0] = __float_as_uint(y.x);                             \
                bf[nt][1] = __float_as_uint(y.y);                             \
            }                                                                 \
            _Pragma("unroll")                                                 \
            for (int mt = 0; mt < 4; mt++)                                    \
                _Pragma("unroll")                                             \
                for (int nt = 0; nt < 4; nt++)                                \
                    mma_tf32(acc[mt][nt], af[mt], bf[nt]);                    \
        }                                                                     \
    } while (0)

// =================== attention scores: S = Q K^T / sqrt(HD) =================
__global__ __launch_bounds__(256)
void scores_mma(const float* __restrict__ q, const float* __restrict__ k,
                float* __restrict__ sc) {
    extern __shared__ float sm[];
    const int tid = threadIdx.x;
    const int wid = tid >> 5, lane = tid & 31;
    const int wm = wid >> 2, wn = wid & 3;
    const int gl = lane >> 2, tg = lane & 3;

    const int bh = blockIdx.z;
    const int b = bh >> 2, h = bh & 3;
    const int m0 = blockIdx.y * 128, n0 = blockIdx.x * 128;
    const int avalid = SS - m0;
    const int bvalid = SS - n0;

    const float* qb = q + (size_t)(b * SS) * EE + h * HD;
    const float* kb = k + (size_t)(b * SS) * EE + h * HD;
    float* cb = sc + (size_t)bh * SP * SP;

    const int srow = tid >> 3, sc4 = tid & 7;

    float acc[4][4][4];
#pragma unroll
    for (int i = 0; i < 4; i++)
#pragma unroll
        for (int j = 0; j < 4; j++)
#pragma unroll
            for (int r = 0; r < 4; r++) acc[i][j][r] = 0.f;

    const int NC = HD >> 5;

    auto stage = [&](int c, int buf) {
        float* ad = sm + buf * (2 * TILEF);
        float* bd = ad + TILEF;
#pragma unroll
        for (int i = 0; i < 4; i++) {
            int row = srow + i * 32;
            bool va = row < avalid, vb = row < bvalid;
            int ra = va ? (m0 + row) : 0;
            int rb = vb ? (n0 + row) : 0;
            cp16z(ad + row * LDSD + sc4 * 4, qb + (size_t)ra * EE + c * 32 + sc4 * 4, va);
            cp16z(bd + row * LDSD + sc4 * 4, kb + (size_t)rb * EE + c * 32 + sc4 * 4, vb);
        }
    };

    stage(0, 0); CP_COMMIT();
    for (int c = 0; c < NC; c++) {
        CP_WAIT0();
        __syncthreads();
        if (c + 1 < NC) { stage(c + 1, (c + 1) & 1); CP_COMMIT(); }
        const int buf = c & 1;
        const float* As = sm + buf * (2 * TILEF) + (wm * 64) * LDSD;
        const float* Bs = sm + buf * (2 * TILEF) + TILEF + (wn * 32) * LDSD;
        MMA_CHUNK_COMPUTE(As, Bs);
    }

    const float scale = 0.07216878364870322f;  // 1/sqrt(192)
#pragma unroll
    for (int mt = 0; mt < 4; mt++) {
        const int r0 = m0 + wm * 64 + mt * 16 + gl;
#pragma unroll
        for (int nt = 0; nt < 4; nt++) {
            const int col = n0 + wn * 32 + nt * 8 + tg * 2;
            if (col < SS) {
                if (r0 < SS) {
                    float2 v; v.x = acc[mt][nt][0] * scale; v.y = acc[mt][nt][1] * scale;
                    *(float2*)(cb + (size_t)r0 * SP + col) = v;
                }
                if (r0 + 8 < SS) {
                    float2 v; v.x = acc[mt][nt][2] * scale; v.y = acc[mt][nt][3] * scale;
                    *(float2*)(cb + (size_t)(r0 + 8) * SP + col) = v;
                }
            }
        }
    }
}

// =================== attention output: O = P @ V ============================
__global__ __launch_bounds__(256)
void attnout_mma(const float* __restrict__ sc, const float* __restrict__ vt,
                 float* __restrict__ o) {
    extern __shared__ float sm[];
    const int tid = threadIdx.x;
    const int wid = tid >> 5, lane = tid & 31;
    const int wm = wid >> 2, wn = wid & 3;
    const int gl = lane >> 2, tg = lane & 3;

    const int bh = blockIdx.z;
    const int b = bh >> 2, h = bh & 3;
    const int m0 = blockIdx.y * 128, n0 = blockIdx.x * 128;
    const int avalid = SS - m0;
    const int bvalid = HD - n0;

    const float* Ab = sc + (size_t)bh * SP * SP;
    const float* Bb = vt + (size_t)bh * HD * SP;
    float* ob = o + (size_t)(b * SS) * EE + h * HD;

    const int srow = tid >> 3, sc4 = tid & 7;

    float acc[4][4][4];
#pragma unroll
    for (int i = 0; i < 4; i++)
#pragma unroll
        for (int j = 0; j < 4; j++)
#pragma unroll
            for (int r = 0; r < 4; r++) acc[i][j][r] = 0.f;

    const int NC = SP >> 5;

    auto stage = [&](int c, int buf) {
        float* ad = sm + buf * (2 * TILEF);
        float* bd = ad + TILEF;
#pragma unroll
        for (int i = 0; i < 4; i++) {
            int row = srow + i * 32;
            bool va = row < avalid, vb = row < bvalid;
            int ra = va ? (m0 + row) : 0;
            int rb = vb ? (n0 + row) : 0;
            cp16z(ad + row * LDSD + sc4 * 4, Ab + (size_t)ra * SP + c * 32 + sc4 * 4, va);
            cp16z(bd + row * LDSD + sc4 * 4, Bb + (size_t)rb * SP + c * 32 + sc4 * 4, vb);
        }
    };

    stage(0, 0); CP_COMMIT();
    for (int c = 0; c < NC; c++) {
        CP_WAIT0();
        __syncthreads();
        if (c + 1 < NC) { stage(c + 1, (c + 1) & 1); CP_COMMIT(); }
        const int buf = c & 1;
        const float* As = sm + buf * (2 * TILEF) + (wm * 64) * LDSD;
        const float* Bs = sm + buf * (2 * TILEF) + TILEF + (wn * 32) * LDSD;
        MMA_CHUNK_COMPUTE(As, Bs);
    }

#pragma unroll
    for (int mt = 0; mt < 4; mt++) {
        const int r0 = m0 + wm * 64 + mt * 16 + gl;
#pragma unroll
        for (int nt = 0; nt < 4; nt++) {
            const int col = n0 + wn * 32 + nt * 8 + tg * 2;
            if (col < HD) {
                if (r0 < SS) {
                    float2 v; v.x = acc[mt][nt][0]; v.y = acc[mt][nt][1];
                    *(float2*)(ob + (size_t)r0 * EE + col) = v;
                }
                if (r0 + 8 < SS) {
                    float2 v; v.x = acc[mt][nt][2]; v.y = acc[mt][nt][3];
                    *(float2*)(ob + (size_t)(r0 + 8) * EE + col) = v;
                }
            }
        }
    }
}

// ---------------- V transpose: v[b,s,h,d] -> vt[bh][d][s padded] ------------
__global__ __launch_bounds__(256)
void vt_kernel(const float* __restrict__ v, float* __restrict__ vt) {
    __shared__ float t[32][33];
    const int bh = blockIdx.z;
    const int b = bh >> 2, h = bh & 3;
    const int s0 = blockIdx.x * 32, d0 = blockIdx.y * 32;
    const int tx = threadIdx.x & 31, ty = threadIdx.x >> 5;

    for (int i = ty; i < 32; i += 8) {
        int s = s0 + i, d = d0 + tx;
        float val = (s < SS) ? v[(size_t)(b * SS + s) * EE + h * HD + d] : 0.f;
        t[tx][i] = val;
    }
    __syncthreads();
    for (int i = ty; i < 32; i += 8) {
        int d = d0 + i, s = s0 + tx;
        vt[((size_t)bh * HD + d) * SP + s] = t[i][tx];
    }
}

// ---------------- LayerNorm over [S,E] per batch ---------------------------
__global__ __launch_bounds__(256)
void ln_reduce_part(const float* __restrict__ x, float* __restrict__ part) {
    const int b = blockIdx.y, j = blockIdx.x;   // j in [0,4)
    const int Q = SE / 16;                      // float4 per quarter
    const float4* p = (const float4*)(x + (size_t)b * SE) + j * Q;
    float s = 0.f, s2 = 0.f;
    for (int i = threadIdx.x; i < Q; i += 256) {
        float4 v = p[i];
        s  += v.x + v.y + v.z + v.w;
        s2 += v.x * v.x + v.y * v.y + v.z * v.z + v.w * v.w;
    }
    __shared__ float sh[8], sh2[8];
#pragma unroll
    for (int o = 16; o > 0; o >>= 1) {
        s  += __shfl_xor_sync(0xffffffffu, s, o);
        s2 += __shfl_xor_sync(0xffffffffu, s2, o);
    }
    int w = threadIdx.x >> 5;
    if ((threadIdx.x & 31) == 0) { sh[w] = s; sh2[w] = s2; }
    __syncthreads();
    if (threadIdx.x == 0) {
        float ts = 0.f, ts2 = 0.f;
#pragma unroll
        for (int i = 0; i < 8; i++) { ts += sh[i]; ts2 += sh2[i]; }
        part[(b * 4 + j) * 2]     = ts;
        part[(b * 4 + j) * 2 + 1] = ts2;
    }
}

__global__ void ln_finalize(const float* __restrict__ part, float* __restrict__ stats) {
    int b = threadIdx.x;
    if (b >= BB) return;
    float s = 0.f, s2 = 0.f;
#pragma unroll
    for (int j = 0; j < 4; j++) {
        s  += part[(b * 4 + j) * 2];
        s2 += part[(b * 4 + j) * 2 + 1];
    }
    float mean = s / (float)SE;
    float var  = s2 / (float)SE - mean * mean;
    stats[2 * b]     = mean;
    stats[2 * b + 1] = rsqrtf(var + LN_EPS);
}

__global__ __launch_bounds__(256)
void ln_apply4(const float4* __restrict__ x, const float4* __restrict__ w,
               const float4* __restrict__ bias, const float* __restrict__ stats,
               float4* __restrict__ out) {
    int idx = blockIdx.x * blockDim.x + threadIdx.x;
    if (idx >= BB * SE / 4) return;
    int b = idx / (SE / 4);
    int i = idx - b * (SE / 4);
    float mean = stats[2 * b], rstd = stats[2 * b + 1];
    float4 xv = x[idx], wv = w[i], bv = bias[i];
    float4 o;
    o.x = (xv.x - mean) * rstd * wv.x + bv.x;
    o.y = (xv.y - mean) * rstd * wv.y + bv.y;
    o.z = (xv.z - mean) * rstd * wv.z + bv.z;
    o.w = (xv.w - mean) * rstd * wv.w + bv.w;
    out[idx] = o;
}

// ---------------- softmax over rows of padded scores -----------------------
__global__ __launch_bounds__(128)
void softmax_k(float* __restrict__ sc) {
    const int bh = blockIdx.y;
    float* p = sc + (size_t)bh * SP * SP + (size_t)blockIdx.x * SP;
    int tid = threadIdx.x;
    __shared__ float redm[4], reds[4];

    float mx = -1e30f;
    for (int i = tid; i < SS; i += 128) mx = fmaxf(mx, p[i]);
#pragma unroll
    for (int o = 16; o > 0; o >>= 1) mx = fmaxf(mx, __shfl_xor_sync(0xffffffffu, mx, o));
    if ((tid & 31) == 0) redm[tid >> 5] = mx;
    __syncthreads();
    mx = fmaxf(fmaxf(redm[0], redm[1]), fmaxf(redm[2], redm[3]));

    float sum = 0.f;
    for (int i = tid; i < SS; i += 128) {
        float e = __expf(p[i] - mx);
        p[i] = e;
        sum += e;
    }
#pragma unroll
    for (int o = 16; o > 0; o >>= 1) sum += __shfl_xor_sync(0xffffffffu, sum, o);
    if ((tid & 31) == 0) reds[tid >> 5] = sum;
    __syncthreads();
    sum = reds[0] + reds[1] + reds[2] + reds[3];
    float inv = 1.0f / sum;
    for (int i = tid; i < SP; i += 128)
        p[i] = (i < SS) ? p[i] * inv : 0.f;
}

// ---------------- launch ----------------------------------------------------
extern "C" void kernel_launch(void* const* d_in, const int* in_sizes, int n_in,
                              void* d_out, int out_size) {
    const float* x      = (const float*)d_in[0];
    const float* conv_w = (const float*)d_in[1];
    const float* conv_b = (const float*)d_in[2];
    const float* wq     = (const float*)d_in[3];
    const float* bq     = (const float*)d_in[4];
    const float* wk     = (const float*)d_in[5];
    const float* bk     = (const float*)d_in[6];
    const float* wv     = (const float*)d_in[7];
    const float* bv     = (const float*)d_in[8];
    const float* wo     = (const float*)d_in[9];
    const float* bo     = (const float*)d_in[10];
    const float* ln1w   = (const float*)d_in[11];
    const float* ln1b   = (const float*)d_in[12];
    const float* ln2w   = (const float*)d_in[13];
    const float* ln2b   = (const float*)d_in[14];
    float* out = (float*)d_out;

    float *emb, *h, *q, *k, *v, *vt, *sc, *ao, *res, *part, *stats;
    cudaGetSymbolAddress((void**)&emb,   g_emb);
    cudaGetSymbolAddress((void**)&h,     g_h);
    cudaGetSymbolAddress((void**)&q,     g_q);
    cudaGetSymbolAddress((void**)&k,     g_k);
    cudaGetSymbolAddress((void**)&v,     g_v);
    cudaGetSymbolAddress((void**)&vt,    g_vt);
    cudaGetSymbolAddress((void**)&sc,    g_scores);
    cudaGetSymbolAddress((void**)&ao,    g_attno);
    cudaGetSymbolAddress((void**)&res,   g_res);
    cudaGetSymbolAddress((void**)&part,  g_part);
    cudaGetSymbolAddress((void**)&stats, g_stats);

    cudaFuncSetAttribute(gemm_embed,
                         cudaFuncAttributeMaxDynamicSharedMemorySize, BIG_SMEM_BYTES);
    cudaFuncSetAttribute(gemm_qkv,
                         cudaFuncAttributeMaxDynamicSharedMemorySize, BIG_SMEM_BYTES);
    cudaFuncSetAttribute(gemm_proj,
                         cudaFuncAttributeMaxDynamicSharedMemorySize, BIG_SMEM_BYTES);
    cudaFuncSetAttribute(scores_mma,
                         cudaFuncAttributeMaxDynamicSharedMemorySize, ATT_SMEM_BYTES);
    cudaFuncSetAttribute(attnout_mma,
                         cudaFuncAttributeMaxDynamicSharedMemorySize, ATT_SMEM_BYTES);

    dim3 big_grid(EE / 256, BSROWS / 128);       // (3, 98)
    dim3 qkv_grid(EE / 256, BSROWS / 128, 3);    // (3, 98, 3)
    dim3 lnr_grid(4, BB);

    // 1. patch embedding GEMM (fused patch gather)
    gemm_embed<<<big_grid, 256, BIG_SMEM_BYTES>>>(x, conv_w, conv_b, emb);
    // 2. LN1
    ln_reduce_part<<<lnr_grid, 256>>>(emb, part);
    ln_finalize<<<1, 64>>>(part, stats);
    ln_apply4<<<(BB * SE / 4 + 255) / 256, 256>>>((const float4*)emb, (const float4*)ln1w,
                                                  (const float4*)ln1b, stats, (float4*)h);
    // 3. QKV (single fused launch)
    gemm_qkv<<<qkv_grid, 256, BIG_SMEM_BYTES>>>(h, wq, wk, wv, bq, bk, bv, q, k, v);
    // 4. attention
    vt_kernel<<<dim3(SP / 32, HD / 32, BB * HH), 256>>>(v, vt);
    scores_mma<<<dim3(2, 2, BB * HH), 256, ATT_SMEM_BYTES>>>(q, k, sc);
    softmax_k<<<dim3(SS, BB * HH), 128>>>(sc);
    attnout_mma<<<dim3(2, 2, BB * HH), 256, ATT_SMEM_BYTES>>>(sc, vt, ao);
    // 5. output projection + residual
    gemm_proj<<<big_grid, 256, BIG_SMEM_BYTES>>>(ao, wo, bo, emb, res);
    // 6. LN2 -> d_out
    ln_reduce_part<<<lnr_grid, 256>>>(res, part);
    ln_finalize<<<1, 64>>>(part, stats);
    ln_apply4<<<(BB * SE / 4 + 255) / 256, 256>>>((const float4*)res, (const float4*)ln2w,
                                                  (const float4*)ln2b, stats, (float4*)out);
}

// round 11
// speedup vs baseline: 1.0601x; 1.0601x over previous
#include <cuda_runtime.h>
#include <math.h>
#include <stdint.h>

#define BB 64
#define SS 196
#define EE 768
#define HH 4
#define HD 192
#define SP 224              /* padded seq (196 -> 224 = 7*32) */
#define GRID14 14
#define BSROWS (BB*SS)      /* 12544 */
#define SE (SS*EE)          /* 150528 */
#define LN_EPS 1e-5f

// ---------------- scratch (static device arrays; no cudaMalloc) -------------
__device__ float g_emb[BSROWS*EE];      // skip1
__device__ float g_h[BSROWS*EE];        // LN1 output
__device__ float g_q[BSROWS*EE];
__device__ float g_k[BSROWS*EE];
__device__ float g_v[BSROWS*EE];
__device__ float g_vt[BB*HH*HD*SP];     // V transposed per head, s padded
__device__ float g_attno[BSROWS*EE];
__device__ float g_res[BSROWS*EE];      // skip1 + proj (pre-LN2)
__device__ float g_part[BB*4*2];        // partial LN sums

// =================== helpers ================================================
__device__ __forceinline__ uint32_t smem_u32(const void* p) {
    uint32_t a;
    asm("{ .reg .u64 t; cvta.to.shared.u64 t, %1; cvt.u32.u64 %0, t; }"
        : "=r"(a) : "l"(p));
    return a;
}

__device__ __forceinline__ void cp16(void* smem_dst, const void* gmem_src) {
    uint32_t s = smem_u32(smem_dst);
    asm volatile("cp.async.cg.shared.global [%0], [%1], 16;"
                 :: "r"(s), "l"(gmem_src) : "memory");
}
__device__ __forceinline__ void cp16z(void* smem_dst, const void* gmem_src, bool v) {
    uint32_t s = smem_u32(smem_dst);
    int sz = v ? 16 : 0;
    asm volatile("cp.async.cg.shared.global [%0], [%1], 16, %2;"
                 :: "r"(s), "l"(gmem_src), "r"(sz) : "memory");
}
#define CP_COMMIT() asm volatile("cp.async.commit_group;" ::: "memory")
#define CP_WAIT0()  asm volatile("cp.async.wait_group 0;" ::: "memory")

// mma.sync m16n8k8 tf32: D(16x8,f32) += A(16x8,tf32) * B(8x8,tf32)
__device__ __forceinline__ void mma_tf32(float* c, const uint32_t* a,
                                         const uint32_t* b) {
    asm volatile(
        "mma.sync.aligned.m16n8k8.row.col.f32.tf32.tf32.f32 "
        "{%0,%1,%2,%3}, {%4,%5,%6,%7}, {%8,%9}, {%0,%1,%2,%3};"
        : "+f"(c[0]), "+f"(c[1]), "+f"(c[2]), "+f"(c[3])
        : "r"(a[0]), "r"(a[1]), "r"(a[2]), "r"(a[3]), "r"(b[0]), "r"(b[1]));
}

// =================== tile framework constants ===============================
#define LDSD 40                       /* padded row stride; 40%32=8 -> */
                                      /* conflict-free LDS.64 fragment loads */
#define TILEF (128 * LDSD)            /* 5120 floats per (A or B) buffer */
#define GEMM_SMEM_BYTES (4 * TILEF * 4)   /* 2 stages x (A+B) = 81920 B */

// k-permutation fragment loads: thread tg holds logical k-cols {kk+2tg,
// kk+2tg+1} (one LDS.64). Valid since the same perm is applied to A and B.
#define MMA_CHUNK_COMPUTE(As, Bs)                                             \
    do {                                                                      \
        _Pragma("unroll")                                                     \
        for (int kk = 0; kk < 32; kk += 8) {                                  \
            uint32_t af[4][4], bf[4][2];                                      \
            _Pragma("unroll")                                                 \
            for (int mt = 0; mt < 4; mt++) {                                  \
                const float2 x0 = *(const float2*)((As) + (mt * 16 + gl) * LDSD + kk + 2 * tg); \
                const float2 x1 = *(const float2*)((As) + (mt * 16 + gl + 8) * LDSD + kk + 2 * tg); \
                af[mt][0] = __float_as_uint(x0.x);                            \
                af[mt][2] = __float_as_uint(x0.y);                            \
                af[mt][1] = __float_as_uint(x1.x);                            \
                af[mt][3] = __float_as_uint(x1.y);                            \
            }                                                                 \
            _Pragma("unroll")                                                 \
            for (int nt = 0; nt < 4; nt++) {                                  \
                const float2 y = *(const float2*)((Bs) + (nt * 8 + gl) * LDSD + kk + 2 * tg); \
                bf[nt][0] = __float_as_uint(y.x);                             \
                bf[nt][1] = __float_as_uint(y.y);                             \
            }                                                                 \
            _Pragma("unroll")                                                 \
            for (int mt = 0; mt < 4; mt++)                                    \
                _Pragma("unroll")                                             \
                for (int nt = 0; nt < 4; nt++)                                \
                    mma_tf32(acc[mt][nt], af[mt], bf[nt]);                    \
        }                                                                     \
    } while (0)

// patch-gather address: row m of the virtual patch matrix, column col
__device__ __forceinline__ const float* embed_addr(const float* x, int m, int col) {
    int b = m / SS, s = m - b * SS;
    int gy = s / GRID14, gx = s - gy * GRID14;
    int ch = col >> 8, r = col & 255;
    int py = r >> 4, px = r & 15;
    return x + (((size_t)(b * 3 + ch) * 224 + (gy * 16 + py)) * 224 + gx * 16 + px);
}

// =================== 2-stage tf32 GEMM body (128x128 tile) ==================
template <int MODE, bool HAS_SKIP>
__device__ __forceinline__ void gemm_body(
    float* sm, const float* __restrict__ A, const float* __restrict__ Bm,
    const float* __restrict__ bias, const float* __restrict__ skip,
    float* __restrict__ C, int M, int N, int K, int m0, int n0) {
    const int tid = threadIdx.x;
    const int wid = tid >> 5, lane = tid & 31;
    const int wm = wid >> 2, wn = wid & 3;
    const int gl = lane >> 2, tg = lane & 3;
    const int srow = tid >> 3, sc4 = tid & 7;

    float acc[4][4][4];
#pragma unroll
    for (int i = 0; i < 4; i++)
#pragma unroll
        for (int j = 0; j < 4; j++)
#pragma unroll
            for (int r = 0; r < 4; r++) acc[i][j][r] = 0.f;

    const int NC = K >> 5;

    auto stage = [&](int c, int buf) {
        float* ad = sm + buf * (2 * TILEF);
        float* bd = ad + TILEF;
        const int colbase = c * 32 + sc4 * 4;
#pragma unroll
        for (int i = 0; i < 4; i++) {
            int row = srow + i * 32;
            const float* asrc;
            if (MODE == 1) asrc = embed_addr(A, m0 + row, colbase);
            else           asrc = A + (size_t)(m0 + row) * K + colbase;
            cp16(ad + row * LDSD + sc4 * 4, asrc);
            cp16(bd + row * LDSD + sc4 * 4, Bm + (size_t)(n0 + row) * K + colbase);
        }
    };

    stage(0, 0); CP_COMMIT();

    for (int c = 0; c < NC; c++) {
        CP_WAIT0();
        __syncthreads();
        if (c + 1 < NC) { stage(c + 1, (c + 1) & 1); CP_COMMIT(); }
        const int buf = c & 1;
        const float* As = sm + buf * (2 * TILEF) + (wm * 64) * LDSD;
        const float* Bs = sm + buf * (2 * TILEF) + TILEF + (wn * 32) * LDSD;
        MMA_CHUNK_COMPUTE(As, Bs);
    }

#pragma unroll
    for (int mt = 0; mt < 4; mt++) {
        const int r0 = m0 + wm * 64 + mt * 16 + gl;
#pragma unroll
        for (int nt = 0; nt < 4; nt++) {
            const int col = n0 + wn * 32 + nt * 8 + tg * 2;
            const float2 bv = *(const float2*)(bias + col);
            float2 v0, v1;
            v0.x = acc[mt][nt][0] + bv.x;
            v0.y = acc[mt][nt][1] + bv.y;
            v1.x = acc[mt][nt][2] + bv.x;
            v1.y = acc[mt][nt][3] + bv.y;
            if (HAS_SKIP) {
                const float2 s0 = *(const float2*)(skip + (size_t)r0 * N + col);
                const float2 s1 = *(const float2*)(skip + (size_t)(r0 + 8) * N + col);
                v0.x += s0.x; v0.y += s0.y;
                v1.x += s1.x; v1.y += s1.y;
            }
            *(float2*)(C + (size_t)r0 * N + col)       = v0;
            *(float2*)(C + (size_t)(r0 + 8) * N + col) = v1;
        }
    }
}

__global__ __launch_bounds__(256)
void gemm_embed(const float* __restrict__ x, const float* __restrict__ Bm,
                const float* __restrict__ bias, float* __restrict__ C) {
    extern __shared__ float sm[];
    gemm_body<1, false>(sm, x, Bm, bias, nullptr, C, BSROWS, EE, EE,
                        blockIdx.y * 128, blockIdx.x * 128);
}

__global__ __launch_bounds__(256)
void gemm_qkv(const float* __restrict__ h,
              const float* __restrict__ wq, const float* __restrict__ wk,
              const float* __restrict__ wv, const float* __restrict__ bq,
              const float* __restrict__ bk, const float* __restrict__ bv,
              float* __restrict__ q, float* __restrict__ k, float* __restrict__ v) {
    extern __shared__ float sm[];
    const int z = blockIdx.z;
    const float* w = (z == 0) ? wq : (z == 1) ? wk : wv;
    const float* b = (z == 0) ? bq : (z == 1) ? bk : bv;
    float* o       = (z == 0) ? q  : (z == 1) ? k  : v;
    gemm_body<0, false>(sm, h, w, b, nullptr, o, BSROWS, EE, EE,
                        blockIdx.y * 128, blockIdx.x * 128);
}

__global__ __launch_bounds__(256)
void gemm_proj(const float* __restrict__ a, const float* __restrict__ w,
               const float* __restrict__ bias, const float* __restrict__ skip,
               float* __restrict__ C) {
    extern __shared__ float sm[];
    gemm_body<0, true>(sm, a, w, bias, skip, C, BSROWS, EE, EE,
                       blockIdx.y * 128, blockIdx.x * 128);
}

// =================== fused attention ========================================
// One CTA per (bh, 128-row tile): S = QK^T (regs) -> masked softmax (no max
// subtract; scores are O(1) for normalized inputs) -> P to smem -> O = P Vt^T.
#define PSTR 232                          /* P row stride: 232%32=8 conflict-free */
#define FA_P_FLOATS (128 * PSTR)          /* 29696 floats */
#define FA_STAGEA_F ((128 + 224) * LDSD)  /* phase-A stage: 14080 floats */
#define FA_VT_F (192 * LDSD)              /* phase-C Vt stage: 7680 floats */
#define FA_SMEM_BYTES ((FA_P_FLOATS + 2 * FA_VT_F) * 4)   /* 180224 B */

__global__ __launch_bounds__(256)
void fused_attn(const float* __restrict__ q, const float* __restrict__ k,
                const float* __restrict__ vt, float* __restrict__ o) {
    extern __shared__ float sm[];
    float* Pbuf   = sm;                     // [128][PSTR]
    float* stageC = sm + FA_P_FLOATS;       // 2 x FA_VT_F  (red buffer in phase B)
    float* red    = stageC;                 // [4][128]

    const int tid = threadIdx.x;
    const int wid = tid >> 5, lane = tid & 31;
    const int wm = wid >> 2, wn = wid & 3;
    const int gl = lane >> 2, tg = lane & 3;
    const int srow = tid >> 3, sc4 = tid & 7;

    const int bh = blockIdx.y;
    const int b = bh >> 2, h = bh & 3;
    const int m0 = blockIdx.x * 128;
    const int avalid = SS - m0;

    const float* qb = q + (size_t)(b * SS) * EE + h * HD;
    const float* kb = k + (size_t)(b * SS) * EE + h * HD;

    // ---------- phase A: S = Q K^T  (warp tile 64 x 56, K=HD in 6 chunks) ----
    float acc[4][7][4];
#pragma unroll
    for (int i = 0; i < 4; i++)
#pragma unroll
        for (int j = 0; j < 7; j++)
#pragma unroll
            for (int r = 0; r < 4; r++) acc[i][j][r] = 0.f;

    auto stageA = [&](int c, int buf) {
        float* ad = sm + buf * FA_STAGEA_F;
        float* bd = ad + 128 * LDSD;
        const int colbase = c * 32 + sc4 * 4;
#pragma unroll
        for (int i = 0; i < 4; i++) {                    // Q: 128 rows
            int row = srow + i * 32;
            bool va = row < avalid;
            int ra = va ? (m0 + row) : 0;
            cp16z(ad + row * LDSD + sc4 * 4, qb + (size_t)ra * EE + colbase, va);
        }
#pragma unroll
        for (int i = 0; i < 7; i++) {                    // K: 224 rows (pad zero)
            int row = srow + i * 32;
            bool vb = row < SS;
            int rb = vb ? row : 0;
            cp16z(bd + row * LDSD + sc4 * 4, kb + (size_t)rb * EE + colbase, vb);
        }
    };

    stageA(0, 0); CP_COMMIT();
    for (int c = 0; c < 6; c++) {
        CP_WAIT0();
        __syncthreads();
        if (c < 5) { stageA(c + 1, (c + 1) & 1); CP_COMMIT(); }
        const float* As = sm + (c & 1) * FA_STAGEA_F + (wm * 64) * LDSD;
        const float* Bs = sm + (c & 1) * FA_STAGEA_F + 128 * LDSD + (wn * 56) * LDSD;
#pragma unroll
        for (int kk = 0; kk < 32; kk += 8) {
            uint32_t af[4][4], bf[7][2];
#pragma unroll
            for (int mt = 0; mt < 4; mt++) {
                const float2 x0 = *(const float2*)(As + (mt * 16 + gl) * LDSD + kk + 2 * tg);
                const float2 x1 = *(const float2*)(As + (mt * 16 + gl + 8) * LDSD + kk + 2 * tg);
                af[mt][0] = __float_as_uint(x0.x);
                af[mt][2] = __float_as_uint(x0.y);
                af[mt][1] = __float_as_uint(x1.x);
                af[mt][3] = __float_as_uint(x1.y);
            }
#pragma unroll
            for (int nt = 0; nt < 7; nt++) {
                const float2 y = *(const float2*)(Bs + (nt * 8 + gl) * LDSD + kk + 2 * tg);
                bf[nt][0] = __float_as_uint(y.x);
                bf[nt][1] = __float_as_uint(y.y);
            }
#pragma unroll
            for (int mt = 0; mt < 4; mt++)
#pragma unroll
                for (int nt = 0; nt < 7; nt++)
                    mma_tf32(acc[mt][nt], af[mt], bf[nt]);
        }
    }
    __syncthreads();   // all warps done reading phase-A staging (overlaps Pbuf)

    // ---------- phase B: masked softmax (no max-subtract) --------------------
    const float scale = 0.07216878364870322f;  // 1/sqrt(192)
    float rs[4][2];
#pragma unroll
    for (int mt = 0; mt < 4; mt++) { rs[mt][0] = 0.f; rs[mt][1] = 0.f; }
#pragma unroll
    for (int mt = 0; mt < 4; mt++)
#pragma unroll
        for (int nt = 0; nt < 7; nt++) {
            const int col = wn * 56 + nt * 8 + tg * 2;
            const bool v0 = col < SS, v1 = (col + 1) < SS;
            float p00 = v0 ? __expf(acc[mt][nt][0] * scale) : 0.f;
            float p01 = v1 ? __expf(acc[mt][nt][1] * scale) : 0.f;
            float p10 = v0 ? __expf(acc[mt][nt][2] * scale) : 0.f;
            float p11 = v1 ? __expf(acc[mt][nt][3] * scale) : 0.f;
            acc[mt][nt][0] = p00; acc[mt][nt][1] = p01;
            acc[mt][nt][2] = p10; acc[mt][nt][3] = p11;
            rs[mt][0] += p00 + p01;
            rs[mt][1] += p10 + p11;
        }
#pragma unroll
    for (int mt = 0; mt < 4; mt++)
#pragma unroll
        for (int s2 = 0; s2 < 2; s2++) {
            rs[mt][s2] += __shfl_xor_sync(0xffffffffu, rs[mt][s2], 1);
            rs[mt][s2] += __shfl_xor_sync(0xffffffffu, rs[mt][s2], 2);
        }
    if (tg == 0) {
#pragma unroll
        for (int mt = 0; mt < 4; mt++) {
            red[wn * 128 + wm * 64 + mt * 16 + gl]     = rs[mt][0];
            red[wn * 128 + wm * 64 + mt * 16 + gl + 8] = rs[mt][1];
        }
    }
    __syncthreads();
    float inv[4][2];
#pragma unroll
    for (int mt = 0; mt < 4; mt++)
#pragma unroll
        for (int s2 = 0; s2 < 2; s2++) {
            const int r = wm * 64 + mt * 16 + gl + s2 * 8;
            float sum = red[r] + red[128 + r] + red[256 + r] + red[384 + r];
            inv[mt][s2] = 1.0f / sum;
        }
    // scale P and store to smem (rows are padded-safe; cols masked to 0)
#pragma unroll
    for (int mt = 0; mt < 4; mt++)
#pragma unroll
        for (int nt = 0; nt < 7; nt++) {
            const int col = wn * 56 + nt * 8 + tg * 2;
            float2 v0, v1;
            v0.x = acc[mt][nt][0] * inv[mt][0];
            v0.y = acc[mt][nt][1] * inv[mt][0];
            v1.x = acc[mt][nt][2] * inv[mt][1];
            v1.y = acc[mt][nt][3] * inv[mt][1];
            *(float2*)(Pbuf + (wm * 64 + mt * 16 + gl) * PSTR + col)     = v0;
            *(float2*)(Pbuf + (wm * 64 + mt * 16 + gl + 8) * PSTR + col) = v1;
        }
    __syncthreads();   // P visible; red reads done before stageC overwrites

    // ---------- phase C: O = P Vt^T  (warp tile 64 x 48, K=SP in 7 chunks) ---
    const float* vb = vt + (size_t)bh * HD * SP;
    float acco[4][6][4];
#pragma unroll
    for (int i = 0; i < 4; i++)
#pragma unroll
        for (int j = 0; j < 6; j++)
#pragma unroll
            for (int r = 0; r < 4; r++) acco[i][j][r] = 0.f;

    auto stageV = [&](int c, int buf) {
        float* dd = stageC + buf * FA_VT_F;
        const int colbase = c * 32 + sc4 * 4;
#pragma unroll
        for (int i = 0; i < 6; i++) {                    // Vt: 192 rows
            int row = srow + i * 32;
            cp16(dd + row * LDSD + sc4 * 4, vb + (size_t)row * SP + colbase);
        }
    };

    stageV(0, 0); CP_COMMIT();
    for (int c = 0; c < 7; c++) {
        CP_WAIT0();
        __syncthreads();
        if (c < 6) { stageV(c + 1, (c + 1) & 1); CP_COMMIT(); }
        const float* As = Pbuf + (wm * 64) * PSTR + c * 32;
        const float* Bs = stageC + (c & 1) * FA_VT_F + (wn * 48) * LDSD;
#pragma unroll
        for (int kk = 0; kk < 32; kk += 8) {
            uint32_t af[4][4], bf[6][2];
#pragma unroll
            for (int mt = 0; mt < 4; mt++) {
                const float2 x0 = *(const float2*)(As + (mt * 16 + gl) * PSTR + kk + 2 * tg);
                const float2 x1 = *(const float2*)(As + (mt * 16 + gl + 8) * PSTR + kk + 2 * tg);
                af[mt][0] = __float_as_uint(x0.x);
                af[mt][2] = __float_as_uint(x0.y);
                af[mt][1] = __float_as_uint(x1.x);
                af[mt][3] = __float_as_uint(x1.y);
            }
#pragma unroll
            for (int nt = 0; nt < 6; nt++) {
                const float2 y = *(const float2*)(Bs + (nt * 8 + gl) * LDSD + kk + 2 * tg);
                bf[nt][0] = __float_as_uint(y.x);
                bf[nt][1] = __float_as_uint(y.y);
            }
#pragma unroll
            for (int mt = 0; mt < 4; mt++)
#pragma unroll
                for (int nt = 0; nt < 6; nt++)
                    mma_tf32(acco[mt][nt], af[mt], bf[nt]);
        }
    }

    // epilogue -> g_attno
    float* ob = o + (size_t)(b * SS) * EE + h * HD;
#pragma unroll
    for (int mt = 0; mt < 4; mt++) {
        const int r0 = m0 + wm * 64 + mt * 16 + gl;
#pragma unroll
        for (int nt = 0; nt < 6; nt++) {
            const int col = wn * 48 + nt * 8 + tg * 2;   // < 192 always
            if (r0 < SS) {
                float2 v; v.x = acco[mt][nt][0]; v.y = acco[mt][nt][1];
                *(float2*)(ob + (size_t)r0 * EE + col) = v;
            }
            if (r0 + 8 < SS) {
                float2 v; v.x = acco[mt][nt][2]; v.y = acco[mt][nt][3];
                *(float2*)(ob + (size_t)(r0 + 8) * EE + col) = v;
            }
        }
    }
}

// ---------------- V transpose: v[b,s,h,d] -> vt[bh][d][s padded] ------------
__global__ __launch_bounds__(256)
void vt_kernel(const float* __restrict__ v, float* __restrict__ vt) {
    __shared__ float t[32][33];
    const int bh = blockIdx.z;
    const int b = bh >> 2, h = bh & 3;
    const int s0 = blockIdx.x * 32, d0 = blockIdx.y * 32;
    const int tx = threadIdx.x & 31, ty = threadIdx.x >> 5;

    for (int i = ty; i < 32; i += 8) {
        int s = s0 + i, d = d0 + tx;
        float val = (s < SS) ? v[(size_t)(b * SS + s) * EE + h * HD + d] : 0.f;
        t[tx][i] = val;
    }
    __syncthreads();
    for (int i = ty; i < 32; i += 8) {
        int d = d0 + i, s = s0 + tx;
        vt[((size_t)bh * HD + d) * SP + s] = t[i][tx];
    }
}

// ---------------- LayerNorm over [S,E] per batch ---------------------------
__global__ __launch_bounds__(256)
void ln_reduce_part(const float* __restrict__ x, float* __restrict__ part) {
    const int b = blockIdx.y, j = blockIdx.x;   // j in [0,4)
    const int Q = SE / 16;
    const float4* p = (const float4*)(x + (size_t)b * SE) + j * Q;
    float s = 0.f, s2 = 0.f;
    for (int i = threadIdx.x; i < Q; i += 256) {
        float4 v = p[i];
        s  += v.x + v.y + v.z + v.w;
        s2 += v.x * v.x + v.y * v.y + v.z * v.z + v.w * v.w;
    }
    __shared__ float sh[8], sh2[8];
#pragma unroll
    for (int o = 16; o > 0; o >>= 1) {
        s  += __shfl_xor_sync(0xffffffffu, s, o);
        s2 += __shfl_xor_sync(0xffffffffu, s2, o);
    }
    int w = threadIdx.x >> 5;
    if ((threadIdx.x & 31) == 0) { sh[w] = s; sh2[w] = s2; }
    __syncthreads();
    if (threadIdx.x == 0) {
        float ts = 0.f, ts2 = 0.f;
#pragma unroll
        for (int i = 0; i < 8; i++) { ts += sh[i]; ts2 += sh2[i]; }
        part[(b * 4 + j) * 2]     = ts;
        part[(b * 4 + j) * 2 + 1] = ts2;
    }
}

// LN apply with inlined finalize (reads the 4 partials per batch directly)
__global__ __launch_bounds__(256)
void ln_apply4(const float4* __restrict__ x, const float4* __restrict__ w,
               const float4* __restrict__ bias, const float* __restrict__ part,
               float4* __restrict__ out) {
    int idx = blockIdx.x * blockDim.x + threadIdx.x;
    if (idx >= BB * SE / 4) return;
    int b = idx / (SE / 4);
    int i = idx - b * (SE / 4);
    float s = 0.f, s2 = 0.f;
#pragma unroll
    for (int j = 0; j < 4; j++) {
        s  += part[(b * 4 + j) * 2];
        s2 += part[(b * 4 + j) * 2 + 1];
    }
    float mean = s / (float)SE;
    float rstd = rsqrtf(s2 / (float)SE - mean * mean + LN_EPS);
    float4 xv = x[idx], wv = w[i], bv = bias[i];
    float4 o;
    o.x = (xv.x - mean) * rstd * wv.x + bv.x;
    o.y = (xv.y - mean) * rstd * wv.y + bv.y;
    o.z = (xv.z - mean) * rstd * wv.z + bv.z;
    o.w = (xv.w - mean) * rstd * wv.w + bv.w;
    out[idx] = o;
}

// ---------------- launch ----------------------------------------------------
extern "C" void kernel_launch(void* const* d_in, const int* in_sizes, int n_in,
                              void* d_out, int out_size) {
    const float* x      = (const float*)d_in[0];
    const float* conv_w = (const float*)d_in[1];
    const float* conv_b = (const float*)d_in[2];
    const float* wq     = (const float*)d_in[3];
    const float* bq     = (const float*)d_in[4];
    const float* wk     = (const float*)d_in[5];
    const float* bk     = (const float*)d_in[6];
    const float* wv     = (const float*)d_in[7];
    const float* bv     = (const float*)d_in[8];
    const float* wo     = (const float*)d_in[9];
    const float* bo     = (const float*)d_in[10];
    const float* ln1w   = (const float*)d_in[11];
    const float* ln1b   = (const float*)d_in[12];
    const float* ln2w   = (const float*)d_in[13];
    const float* ln2b   = (const float*)d_in[14];
    float* out = (float*)d_out;

    float *emb, *h, *q, *k, *v, *vt, *ao, *res, *part;
    cudaGetSymbolAddress((void**)&emb,   g_emb);
    cudaGetSymbolAddress((void**)&h,     g_h);
    cudaGetSymbolAddress((void**)&q,     g_q);
    cudaGetSymbolAddress((void**)&k,     g_k);
    cudaGetSymbolAddress((void**)&v,     g_v);
    cudaGetSymbolAddress((void**)&vt,    g_vt);
    cudaGetSymbolAddress((void**)&ao,    g_attno);
    cudaGetSymbolAddress((void**)&res,   g_res);
    cudaGetSymbolAddress((void**)&part,  g_part);

    cudaFuncSetAttribute(gemm_embed,
                         cudaFuncAttributeMaxDynamicSharedMemorySize, GEMM_SMEM_BYTES);
    cudaFuncSetAttribute(gemm_qkv,
                         cudaFuncAttributeMaxDynamicSharedMemorySize, GEMM_SMEM_BYTES);
    cudaFuncSetAttribute(gemm_proj,
                         cudaFuncAttributeMaxDynamicSharedMemorySize, GEMM_SMEM_BYTES);
    cudaFuncSetAttribute(fused_attn,
                         cudaFuncAttributeMaxDynamicSharedMemorySize, FA_SMEM_BYTES);

    dim3 tc_grid(EE / 128, BSROWS / 128);       // (6, 98)
    dim3 qkv_grid(EE / 128, BSROWS / 128, 3);   // (6, 98, 3)
    dim3 lnr_grid(4, BB);

    // 1. patch embedding GEMM (fused patch gather)
    gemm_embed<<<tc_grid, 256, GEMM_SMEM_BYTES>>>(x, conv_w, conv_b, emb);
    // 2. LN1
    ln_reduce_part<<<lnr_grid, 256>>>(emb, part);
    ln_apply4<<<(BB * SE / 4 + 255) / 256, 256>>>((const float4*)emb, (const float4*)ln1w,
                                                  (const float4*)ln1b, part, (float4*)h);
    // 3. QKV (single fused launch)
    gemm_qkv<<<qkv_grid, 256, GEMM_SMEM_BYTES>>>(h, wq, wk, wv, bq, bk, bv, q, k, v);
    // 4. attention (fused scores+softmax+PV)
    vt_kernel<<<dim3(SP / 32, HD / 32, BB * HH), 256>>>(v, vt);
    fused_attn<<<dim3(2, BB * HH), 256, FA_SMEM_BYTES>>>(q, k, vt, ao);
    // 5. output projection + residual
    gemm_proj<<<tc_grid, 256, GEMM_SMEM_BYTES>>>(ao, wo, bo, emb, res);
    // 6. LN2 -> d_out
    ln_reduce_part<<<lnr_grid, 256>>>(res, part);
    ln_apply4<<<(BB * SE / 4 + 255) / 256, 256>>>((const float4*)res, (const float4*)ln2w,
                                                  (const float4*)ln2b, part, (float4*)out);
}

// round 12
// speedup vs baseline: 1.5147x; 1.4289x over previous
#include <cuda_runtime.h>
#include <cuda_fp16.h>
#include <math.h>
#include <stdint.h>

#define BB 64
#define SS 196
#define EE 768
#define HH 4
#define HD 192
#define SP 224              /* padded seq (196 -> 224 = 7*32) */
#define GRID14 14
#define BSROWS (BB*SS)      /* 12544 */
#define SE (SS*EE)          /* 150528 */
#define LN_EPS 1e-5f

// ---------------- scratch (static device arrays; no cudaMalloc) -------------
__device__ float  g_emb[BSROWS*EE];       // skip1 (fp32)
__device__ float  g_res[BSROWS*EE];       // pre-LN2 (fp32)
__device__ float  g_part[BB*4*2];         // partial LN sums
__device__ __half g_ph[BSROWS*EE];        // patches fp16
__device__ __half g_hh[BSROWS*EE];        // LN1 out fp16
__device__ __half g_qh[BSROWS*EE];
__device__ __half g_kh[BSROWS*EE];
__device__ __half g_vh[BSROWS*EE];
__device__ __half g_vth[BB*HH*HD*SP];     // V transposed fp16
__device__ __half g_aoh[BSROWS*EE];       // attention out fp16
__device__ __half g_w16[5*EE*EE];         // conv_w, wq, wk, wv, wo fp16

// =================== helpers ================================================
__device__ __forceinline__ uint32_t smem_u32(const void* p) {
    uint32_t a;
    asm("{ .reg .u64 t; cvta.to.shared.u64 t, %1; cvt.u32.u64 %0, t; }"
        : "=r"(a) : "l"(p));
    return a;
}
__device__ __forceinline__ void cp16(void* smem_dst, const void* gmem_src) {
    uint32_t s = smem_u32(smem_dst);
    asm volatile("cp.async.cg.shared.global [%0], [%1], 16;"
                 :: "r"(s), "l"(gmem_src) : "memory");
}
__device__ __forceinline__ void cp16z(void* smem_dst, const void* gmem_src, bool v) {
    uint32_t s = smem_u32(smem_dst);
    int sz = v ? 16 : 0;
    asm volatile("cp.async.cg.shared.global [%0], [%1], 16, %2;"
                 :: "r"(s), "l"(gmem_src), "r"(sz) : "memory");
}
#define CP_COMMIT() asm volatile("cp.async.commit_group;" ::: "memory")
#define CP_WAIT0()  asm volatile("cp.async.wait_group 0;" ::: "memory")

// mma.sync m16n8k16 fp16: D(f32) += A(f16) * B(f16)
__device__ __forceinline__ void mma_f16(float* c, const uint32_t* a,
                                        const uint32_t* b) {
    asm volatile(
        "mma.sync.aligned.m16n8k16.row.col.f32.f16.f16.f32 "
        "{%0,%1,%2,%3}, {%4,%5,%6,%7}, {%8,%9}, {%0,%1,%2,%3};"
        : "+f"(c[0]), "+f"(c[1]), "+f"(c[2]), "+f"(c[3])
        : "r"(a[0]), "r"(a[1]), "r"(a[2]), "r"(a[3]), "r"(b[0]), "r"(b[1]));
}

// epilogue store helpers (float2 -> fp32 or fp16 destination)
__device__ __forceinline__ void store2(float* C, size_t off, float2 v) {
    *(float2*)(C + off) = v;
}
__device__ __forceinline__ void store2(__half* C, size_t off, float2 v) {
    *(__half2*)(C + off) = __floats2half2_rn(v.x, v.y);
}

// =================== tile framework constants ===============================
// stage row stride 48 halves (96 B): fragment uint2 loads hit banks
// gl*24 + 2tg (mod 32) -> all 16 lanes distinct -> conflict-free.
#define LDH 48
#define TILEH (128 * LDH)                 /* 6144 halves per operand buffer */
#define GEMM_SMEM_BYTES (4 * TILEH * 2)   /* 2 stages x (A+B) = 49152 B */

// k-permutation: thread tg holds logical k {4tg..4tg+3} per 16-k step
// (one uint2 = 4 halves). Same perm on A and B -> result unchanged.
#define MMA16_CHUNK(As, Bs, NT, accv)                                         \
    do {                                                                      \
        _Pragma("unroll")                                                     \
        for (int kk = 0; kk < 32; kk += 16) {                                 \
            uint32_t af[4][4], bf[NT][2];                                     \
            _Pragma("unroll")                                                 \
            for (int mt = 0; mt < 4; mt++) {                                  \
                const uint2 x0 = *(const uint2*)((As) + (mt * 16 + gl) * LDH + kk + 4 * tg); \
                const uint2 x1 = *(const uint2*)((As) + (mt * 16 + gl + 8) * LDH + kk + 4 * tg); \
                af[mt][0] = x0.x; af[mt][2] = x0.y;                           \
                af[mt][1] = x1.x; af[mt][3] = x1.y;                           \
            }                                                                 \
            _Pragma("unroll")                                                 \
            for (int nt = 0; nt < NT; nt++) {                                 \
                const uint2 y = *(const uint2*)((Bs) + (nt * 8 + gl) * LDH + kk + 4 * tg); \
                bf[nt][0] = y.x; bf[nt][1] = y.y;                             \
            }                                                                 \
            _Pragma("unroll")                                                 \
            for (int mt = 0; mt < 4; mt++)                                    \
                _Pragma("unroll")                                             \
                for (int nt = 0; nt < NT; nt++)                               \
                    mma_f16(accv[mt][nt], af[mt], bf[nt]);                    \
        }                                                                     \
    } while (0)

// =================== fp16 GEMM body (128x128 tile, 2-stage) =================
// C[M,N] = A[M,K]*B[N,K]^T + bias (+skip). A,B fp16; C fp32 or fp16.
template <bool HAS_SKIP, typename OutT>
__device__ __forceinline__ void gemm_body16(
    __half* smh, const __half* __restrict__ A, const __half* __restrict__ Bm,
    const float* __restrict__ bias, const float* __restrict__ skip,
    OutT* __restrict__ C, int M, int N, int K, int m0, int n0) {
    const int tid = threadIdx.x;
    const int wid = tid >> 5, lane = tid & 31;
    const int wm = wid >> 2, wn = wid & 3;
    const int gl = lane >> 2, tg = lane & 3;
    const int srow64 = tid >> 2, sc16 = tid & 3;

    float acc[4][4][4];
#pragma unroll
    for (int i = 0; i < 4; i++)
#pragma unroll
        for (int j = 0; j < 4; j++)
#pragma unroll
            for (int r = 0; r < 4; r++) acc[i][j][r] = 0.f;

    const int NC = K >> 5;

    auto stage = [&](int c, int buf) {
        __half* ad = smh + buf * (2 * TILEH);
        __half* bd = ad + TILEH;
        const int colbase = c * 32 + sc16 * 8;
#pragma unroll
        for (int i = 0; i < 2; i++) {
            int row = srow64 + i * 64;
            cp16(ad + row * LDH + sc16 * 8, A + (size_t)(m0 + row) * K + colbase);
            cp16(bd + row * LDH + sc16 * 8, Bm + (size_t)(n0 + row) * K + colbase);
        }
    };

    stage(0, 0); CP_COMMIT();

    for (int c = 0; c < NC; c++) {
        CP_WAIT0();
        __syncthreads();
        if (c + 1 < NC) { stage(c + 1, (c + 1) & 1); CP_COMMIT(); }
        const __half* As = smh + (c & 1) * (2 * TILEH) + (wm * 64) * LDH;
        const __half* Bs = smh + (c & 1) * (2 * TILEH) + TILEH + (wn * 32) * LDH;
        MMA16_CHUNK(As, Bs, 4, acc);
    }

#pragma unroll
    for (int mt = 0; mt < 4; mt++) {
        const int r0 = m0 + wm * 64 + mt * 16 + gl;
#pragma unroll
        for (int nt = 0; nt < 4; nt++) {
            const int col = n0 + wn * 32 + nt * 8 + tg * 2;
            const float2 bv = *(const float2*)(bias + col);
            float2 v0, v1;
            v0.x = acc[mt][nt][0] + bv.x;
            v0.y = acc[mt][nt][1] + bv.y;
            v1.x = acc[mt][nt][2] + bv.x;
            v1.y = acc[mt][nt][3] + bv.y;
            if (HAS_SKIP) {
                const float2 s0 = *(const float2*)(skip + (size_t)r0 * N + col);
                const float2 s1 = *(const float2*)(skip + (size_t)(r0 + 8) * N + col);
                v0.x += s0.x; v0.y += s0.y;
                v1.x += s1.x; v1.y += s1.y;
            }
            store2(C, (size_t)r0 * N + col, v0);
            store2(C, (size_t)(r0 + 8) * N + col, v1);
        }
    }
}

__global__ __launch_bounds__(256)
void gemm_embed(const __half* __restrict__ A, const __half* __restrict__ Bm,
                const float* __restrict__ bias, float* __restrict__ C) {
    extern __shared__ __half smh[];
    gemm_body16<false, float>(smh, A, Bm, bias, nullptr, C, BSROWS, EE, EE,
                              blockIdx.y * 128, blockIdx.x * 128);
}

__global__ __launch_bounds__(256)
void gemm_qkv(const __half* __restrict__ h, const __half* __restrict__ w16,
              const float* __restrict__ bq, const float* __restrict__ bk,
              const float* __restrict__ bv,
              __half* __restrict__ q, __half* __restrict__ k, __half* __restrict__ v) {
    extern __shared__ __half smh[];
    const int z = blockIdx.z;
    const __half* w = w16 + (size_t)(1 + z) * EE * EE;
    const float* b = (z == 0) ? bq : (z == 1) ? bk : bv;
    __half* o      = (z == 0) ? q  : (z == 1) ? k  : v;
    gemm_body16<false, __half>(smh, h, w, b, nullptr, o, BSROWS, EE, EE,
                               blockIdx.y * 128, blockIdx.x * 128);
}

__global__ __launch_bounds__(256)
void gemm_proj(const __half* __restrict__ a, const __half* __restrict__ w,
               const float* __restrict__ bias, const float* __restrict__ skip,
               float* __restrict__ C) {
    extern __shared__ __half smh[];
    gemm_body16<true, float>(smh, a, w, bias, skip, C, BSROWS, EE, EE,
                             blockIdx.y * 128, blockIdx.x * 128);
}

// =================== fused attention (fp16 operands) ========================
#define PSTRH 240                          /* P row stride in halves; gl*24+2tg banks ok */
#define FA_P_BYTES (128 * PSTRH * 2)       /* 61440 B */
#define FA_STAGEA_H ((128 + 224) * LDH)    /* 16896 halves per stage */
#define FA_VT_H (192 * LDH)                /* 9216 halves per stage */
#define FA_SMEM_BYTES (FA_P_BYTES + 2 * FA_STAGEA_H * 2)   /* 129024 B */

__global__ __launch_bounds__(256)
void fused_attn(const __half* __restrict__ q, const __half* __restrict__ k,
                const __half* __restrict__ vt, __half* __restrict__ o) {
    extern __shared__ __half smh[];
    __half* Pbuf   = smh;                         // [128][PSTRH]
    __half* stageA = smh + 128 * PSTRH;           // 2 x FA_STAGEA_H
    float*  red    = (float*)stageA;              // [4][128] (phase B only)

    const int tid = threadIdx.x;
    const int wid = tid >> 5, lane = tid & 31;
    const int wm = wid >> 2, wn = wid & 3;
    const int gl = lane >> 2, tg = lane & 3;
    const int srow64 = tid >> 2, sc16 = tid & 3;

    const int bh = blockIdx.y;
    const int b = bh >> 2, h = bh & 3;
    const int m0 = blockIdx.x * 128;
    const int avalid = SS - m0;

    const __half* qb = q + (size_t)(b * SS) * EE + h * HD;
    const __half* kb = k + (size_t)(b * SS) * EE + h * HD;

    // ---------- phase A: S = Q K^T (warp 64x56, K=HD, 6 chunks) -------------
    float acc[4][7][4];
#pragma unroll
    for (int i = 0; i < 4; i++)
#pragma unroll
        for (int j = 0; j < 7; j++)
#pragma unroll
            for (int r = 0; r < 4; r++) acc[i][j][r] = 0.f;

    auto stA = [&](int c, int buf) {
        __half* ad = stageA + buf * FA_STAGEA_H;
        __half* bd = ad + 128 * LDH;
        const int colbase = c * 32 + sc16 * 8;
#pragma unroll
        for (int i = 0; i < 2; i++) {                 // Q: 128 rows
            int row = srow64 + i * 64;
            bool va = row < avalid;
            int ra = va ? (m0 + row) : 0;
            cp16z(ad + row * LDH + sc16 * 8, qb + (size_t)ra * EE + colbase, va);
        }
#pragma unroll
        for (int i = 0; i < 4; i++) {                 // K: 224 rows (zero pad)
            int row = srow64 + i * 64;
            if (row < 224) {
                bool vb = row < SS;
                int rb = vb ? row : 0;
                cp16z(bd + row * LDH + sc16 * 8, kb + (size_t)rb * EE + colbase, vb);
            }
        }
    };

    stA(0, 0); CP_COMMIT();
    for (int c = 0; c < 6; c++) {
        CP_WAIT0();
        __syncthreads();
        if (c < 5) { stA(c + 1, (c + 1) & 1); CP_COMMIT(); }
        const __half* As = stageA + (c & 1) * FA_STAGEA_H + (wm * 64) * LDH;
        const __half* Bs = stageA + (c & 1) * FA_STAGEA_H + 128 * LDH + (wn * 56) * LDH;
        MMA16_CHUNK(As, Bs, 7, acc);
    }
    __syncthreads();

    // ---------- phase B: masked softmax (no max subtract) -------------------
    const float scale = 0.07216878364870322f;  // 1/sqrt(192)
    float rs[4][2];
#pragma unroll
    for (int mt = 0; mt < 4; mt++) { rs[mt][0] = 0.f; rs[mt][1] = 0.f; }
#pragma unroll
    for (int mt = 0; mt < 4; mt++)
#pragma unroll
        for (int nt = 0; nt < 7; nt++) {
            const int col = wn * 56 + nt * 8 + tg * 2;
            const bool v0 = col < SS, v1 = (col + 1) < SS;
            float p00 = v0 ? __expf(acc[mt][nt][0] * scale) : 0.f;
            float p01 = v1 ? __expf(acc[mt][nt][1] * scale) : 0.f;
            float p10 = v0 ? __expf(acc[mt][nt][2] * scale) : 0.f;
            float p11 = v1 ? __expf(acc[mt][nt][3] * scale) : 0.f;
            acc[mt][nt][0] = p00; acc[mt][nt][1] = p01;
            acc[mt][nt][2] = p10; acc[mt][nt][3] = p11;
            rs[mt][0] += p00 + p01;
            rs[mt][1] += p10 + p11;
        }
#pragma unroll
    for (int mt = 0; mt < 4; mt++)
#pragma unroll
        for (int s2 = 0; s2 < 2; s2++) {
            rs[mt][s2] += __shfl_xor_sync(0xffffffffu, rs[mt][s2], 1);
            rs[mt][s2] += __shfl_xor_sync(0xffffffffu, rs[mt][s2], 2);
        }
    if (tg == 0) {
#pragma unroll
        for (int mt = 0; mt < 4; mt++) {
            red[wn * 128 + wm * 64 + mt * 16 + gl]     = rs[mt][0];
            red[wn * 128 + wm * 64 + mt * 16 + gl + 8] = rs[mt][1];
        }
    }
    __syncthreads();
    float inv[4][2];
#pragma unroll
    for (int mt = 0; mt < 4; mt++)
#pragma unroll
        for (int s2 = 0; s2 < 2; s2++) {
            const int r = wm * 64 + mt * 16 + gl + s2 * 8;
            float sum = red[r] + red[128 + r] + red[256 + r] + red[384 + r];
            inv[mt][s2] = 1.0f / sum;
        }
#pragma unroll
    for (int mt = 0; mt < 4; mt++)
#pragma unroll
        for (int nt = 0; nt < 7; nt++) {
            const int col = wn * 56 + nt * 8 + tg * 2;
            *(__half2*)(Pbuf + (wm * 64 + mt * 16 + gl) * PSTRH + col) =
                __floats2half2_rn(acc[mt][nt][0] * inv[mt][0], acc[mt][nt][1] * inv[mt][0]);
            *(__half2*)(Pbuf + (wm * 64 + mt * 16 + gl + 8) * PSTRH + col) =
                __floats2half2_rn(acc[mt][nt][2] * inv[mt][1], acc[mt][nt][3] * inv[mt][1]);
        }
    __syncthreads();   // P visible; red reads done before stage reuse

    // ---------- phase C: O = P Vt^T (warp 64x48, K=SP, 7 chunks) ------------
    const __half* vb = vt + (size_t)bh * HD * SP;
    float acco[4][6][4];
#pragma unroll
    for (int i = 0; i < 4; i++)
#pragma unroll
        for (int j = 0; j < 6; j++)
#pragma unroll
            for (int r = 0; r < 4; r++) acco[i][j][r] = 0.f;

    auto stV = [&](int c, int buf) {
        __half* dd = stageA + buf * FA_VT_H;
        const int colbase = c * 32 + sc16 * 8;
#pragma unroll
        for (int i = 0; i < 3; i++) {                 // Vt: 192 rows
            int row = srow64 + i * 64;
            cp16(dd + row * LDH + sc16 * 8, vb + (size_t)row * SP + colbase);
        }
    };

    stV(0, 0); CP_COMMIT();
    for (int c = 0; c < 7; c++) {
        CP_WAIT0();
        __syncthreads();
        if (c < 6) { stV(c + 1, (c + 1) & 1); CP_COMMIT(); }
        const __half* As = Pbuf + (wm * 64) * PSTRH + c * 32;
        const __half* Bs = stageA + (c & 1) * FA_VT_H + (wn * 48) * LDH;
#pragma unroll
        for (int kk = 0; kk < 32; kk += 16) {
            uint32_t af[4][4], bf[6][2];
#pragma unroll
            for (int mt = 0; mt < 4; mt++) {
                const uint2 x0 = *(const uint2*)(As + (mt * 16 + gl) * PSTRH + kk + 4 * tg);
                const uint2 x1 = *(const uint2*)(As + (mt * 16 + gl + 8) * PSTRH + kk + 4 * tg);
                af[mt][0] = x0.x; af[mt][2] = x0.y;
                af[mt][1] = x1.x; af[mt][3] = x1.y;
            }
#pragma unroll
            for (int nt = 0; nt < 6; nt++) {
                const uint2 y = *(const uint2*)(Bs + (nt * 8 + gl) * LDH + kk + 4 * tg);
                bf[nt][0] = y.x; bf[nt][1] = y.y;
            }
#pragma unroll
            for (int mt = 0; mt < 4; mt++)
#pragma unroll
                for (int nt = 0; nt < 6; nt++)
                    mma_f16(acco[mt][nt], af[mt], bf[nt]);
        }
    }

    __half* ob = o + (size_t)(b * SS) * EE + h * HD;
#pragma unroll
    for (int mt = 0; mt < 4; mt++) {
        const int r0 = m0 + wm * 64 + mt * 16 + gl;
#pragma unroll
        for (int nt = 0; nt < 6; nt++) {
            const int col = wn * 48 + nt * 8 + tg * 2;   // < 192 always
            if (r0 < SS) {
                float2 v; v.x = acco[mt][nt][0]; v.y = acco[mt][nt][1];
                store2(ob, (size_t)r0 * EE + col, v);
            }
            if (r0 + 8 < SS) {
                float2 v; v.x = acco[mt][nt][2]; v.y = acco[mt][nt][3];
                store2(ob, (size_t)(r0 + 8) * EE + col, v);
            }
        }
    }
}

// ---------------- weight conversion: 5 matrices fp32 -> fp16 ----------------
__global__ __launch_bounds__(256)
void cvt_weights(const float4* __restrict__ w0, const float4* __restrict__ w1,
                 const float4* __restrict__ w2, const float4* __restrict__ w3,
                 const float4* __restrict__ w4, __half* __restrict__ dst) {
    const int QN = EE * EE / 4;
    int idx = blockIdx.x * blockDim.x + threadIdx.x;
    if (idx >= 5 * QN) return;
    int which = idx / QN, j = idx - which * QN;
    const float4* src = (which == 0) ? w0 : (which == 1) ? w1 :
                        (which == 2) ? w2 : (which == 3) ? w3 : w4;
    float4 v = src[j];
    __half2 h0 = __floats2half2_rn(v.x, v.y);
    __half2 h1 = __floats2half2_rn(v.z, v.w);
    uint2 u;
    u.x = *(uint32_t*)&h0;
    u.y = *(uint32_t*)&h1;
    *(uint2*)(dst + (size_t)which * EE * EE + (size_t)j * 4) = u;
}

// ---------------- patch gather -> fp16 (read-linear over x) -----------------
__global__ __launch_bounds__(256)
void patch16(const float* __restrict__ x, __half* __restrict__ out) {
    int idx = blockIdx.x * blockDim.x + threadIdx.x;
    if (idx >= BB * 3 * 224 * 224) return;
    int xi = idx % 224;
    int rest = idx / 224;
    int y = rest % 224;
    rest /= 224;
    int ch = rest % 3;
    int b = rest / 3;
    int s = (y >> 4) * GRID14 + (xi >> 4);
    int col = ch * 256 + (y & 15) * 16 + (xi & 15);
    out[(size_t)(b * SS + s) * EE + col] = __float2half(x[idx]);
}

// ---------------- V transpose fp16 ------------------------------------------
__global__ __launch_bounds__(256)
void vt_kernel(const __half* __restrict__ v, __half* __restrict__ vt) {
    __shared__ __half t[32][34];
    const int bh = blockIdx.z;
    const int b = bh >> 2, h = bh & 3;
    const int s0 = blockIdx.x * 32, d0 = blockIdx.y * 32;
    const int tx = threadIdx.x & 31, ty = threadIdx.x >> 5;

    for (int i = ty; i < 32; i += 8) {
        int s = s0 + i, d = d0 + tx;
        __half val = (s < SS) ? v[(size_t)(b * SS + s) * EE + h * HD + d] : __half(0.f);
        t[tx][i] = val;
    }
    __syncthreads();
    for (int i = ty; i < 32; i += 8) {
        int d = d0 + i, s = s0 + tx;
        vt[((size_t)bh * HD + d) * SP + s] = t[i][tx];
    }
}

// ---------------- LayerNorm over [S,E] per batch ----------------------------
__global__ __launch_bounds__(256)
void ln_reduce_part(const float* __restrict__ x, float* __restrict__ part) {
    const int b = blockIdx.y, j = blockIdx.x;
    const int Q = SE / 16;
    const float4* p = (const float4*)(x + (size_t)b * SE) + j * Q;
    float s = 0.f, s2 = 0.f;
    for (int i = threadIdx.x; i < Q; i += 256) {
        float4 v = p[i];
        s  += v.x + v.y + v.z + v.w;
        s2 += v.x * v.x + v.y * v.y + v.z * v.z + v.w * v.w;
    }
    __shared__ float sh[8], sh2[8];
#pragma unroll
    for (int o = 16; o > 0; o >>= 1) {
        s  += __shfl_xor_sync(0xffffffffu, s, o);
        s2 += __shfl_xor_sync(0xffffffffu, s2, o);
    }
    int w = threadIdx.x >> 5;
    if ((threadIdx.x & 31) == 0) { sh[w] = s; sh2[w] = s2; }
    __syncthreads();
    if (threadIdx.x == 0) {
        float ts = 0.f, ts2 = 0.f;
#pragma unroll
        for (int i = 0; i < 8; i++) { ts += sh[i]; ts2 += sh2[i]; }
        part[(b * 4 + j) * 2]     = ts;
        part[(b * 4 + j) * 2 + 1] = ts2;
    }
}

__device__ __forceinline__ void ln_store4(float* out, int idx, float4 o) {
    ((float4*)out)[idx] = o;
}
__device__ __forceinline__ void ln_store4(__half* out, int idx, float4 o) {
    __half2 h0 = __floats2half2_rn(o.x, o.y);
    __half2 h1 = __floats2half2_rn(o.z, o.w);
    uint2 u;
    u.x = *(uint32_t*)&h0;
    u.y = *(uint32_t*)&h1;
    ((uint2*)out)[idx] = u;
}

template <typename OutT>
__global__ __launch_bounds__(256)
void ln_apply4(const float4* __restrict__ x, const float4* __restrict__ w,
               const float4* __restrict__ bias, const float* __restrict__ part,
               OutT* __restrict__ out) {
    int idx = blockIdx.x * blockDim.x + threadIdx.x;
    if (idx >= BB * SE / 4) return;
    int b = idx / (SE / 4);
    int i = idx - b * (SE / 4);
    float s = 0.f, s2 = 0.f;
#pragma unroll
    for (int j = 0; j < 4; j++) {
        s  += part[(b * 4 + j) * 2];
        s2 += part[(b * 4 + j) * 2 + 1];
    }
    float mean = s / (float)SE;
    float rstd = rsqrtf(s2 / (float)SE - mean * mean + LN_EPS);
    float4 xv = x[idx], wv = w[i], bv = bias[i];
    float4 o;
    o.x = (xv.x - mean) * rstd * wv.x + bv.x;
    o.y = (xv.y - mean) * rstd * wv.y + bv.y;
    o.z = (xv.z - mean) * rstd * wv.z + bv.z;
    o.w = (xv.w - mean) * rstd * wv.w + bv.w;
    ln_store4(out, idx, o);
}

// ---------------- launch ----------------------------------------------------
extern "C" void kernel_launch(void* const* d_in, const int* in_sizes, int n_in,
                              void* d_out, int out_size) {
    const float* x      = (const float*)d_in[0];
    const float* conv_w = (const float*)d_in[1];
    const float* conv_b = (const float*)d_in[2];
    const float* wq     = (const float*)d_in[3];
    const float* bq     = (const float*)d_in[4];
    const float* wk     = (const float*)d_in[5];
    const float* bk     = (const float*)d_in[6];
    const float* wv     = (const float*)d_in[7];
    const float* bv     = (const float*)d_in[8];
    const float* wo     = (const float*)d_in[9];
    const float* bo     = (const float*)d_in[10];
    const float* ln1w   = (const float*)d_in[11];
    const float* ln1b   = (const float*)d_in[12];
    const float* ln2w   = (const float*)d_in[13];
    const float* ln2b   = (const float*)d_in[14];
    float* out = (float*)d_out;

    float *emb, *res, *part;
    __half *ph, *hh, *qh, *kh, *vh, *vth, *aoh, *w16;
    cudaGetSymbolAddress((void**)&emb,  g_emb);
    cudaGetSymbolAddress((void**)&res,  g_res);
    cudaGetSymbolAddress((void**)&part, g_part);
    cudaGetSymbolAddress((void**)&ph,   g_ph);
    cudaGetSymbolAddress((void**)&hh,   g_hh);
    cudaGetSymbolAddress((void**)&qh,   g_qh);
    cudaGetSymbolAddress((void**)&kh,   g_kh);
    cudaGetSymbolAddress((void**)&vh,   g_vh);
    cudaGetSymbolAddress((void**)&vth,  g_vth);
    cudaGetSymbolAddress((void**)&aoh,  g_aoh);
    cudaGetSymbolAddress((void**)&w16,  g_w16);

    cudaFuncSetAttribute(gemm_embed,
                         cudaFuncAttributeMaxDynamicSharedMemorySize, GEMM_SMEM_BYTES);
    cudaFuncSetAttribute(gemm_qkv,
                         cudaFuncAttributeMaxDynamicSharedMemorySize, GEMM_SMEM_BYTES);
    cudaFuncSetAttribute(gemm_proj,
                         cudaFuncAttributeMaxDynamicSharedMemorySize, GEMM_SMEM_BYTES);
    cudaFuncSetAttribute(fused_attn,
                         cudaFuncAttributeMaxDynamicSharedMemorySize, FA_SMEM_BYTES);

    dim3 tc_grid(EE / 128, BSROWS / 128);       // (6, 98)
    dim3 qkv_grid(EE / 128, BSROWS / 128, 3);   // (6, 98, 3)
    dim3 lnr_grid(4, BB);

    // 0. conversions (weights + patches)
    cvt_weights<<<(5 * EE * EE / 4 + 255) / 256, 256>>>(
        (const float4*)conv_w, (const float4*)wq, (const float4*)wk,
        (const float4*)wv, (const float4*)wo, w16);
    patch16<<<(BB * 3 * 224 * 224 + 255) / 256, 256>>>(x, ph);
    // 1. patch embedding GEMM
    gemm_embed<<<tc_grid, 256, GEMM_SMEM_BYTES>>>(ph, w16, conv_b, emb);
    // 2. LN1 -> fp16 h
    ln_reduce_part<<<lnr_grid, 256>>>(emb, part);
    ln_apply4<__half><<<(BB * SE / 4 + 255) / 256, 256>>>(
        (const float4*)emb, (const float4*)ln1w, (const float4*)ln1b, part, hh);
    // 3. QKV
    gemm_qkv<<<qkv_grid, 256, GEMM_SMEM_BYTES>>>(hh, w16, bq, bk, bv, qh, kh, vh);
    // 4. attention
    vt_kernel<<<dim3(SP / 32, HD / 32, BB * HH), 256>>>(vh, vth);
    fused_attn<<<dim3(2, BB * HH), 256, FA_SMEM_BYTES>>>(qh, kh, vth, aoh);
    // 5. output projection + residual
    gemm_proj<<<tc_grid, 256, GEMM_SMEM_BYTES>>>(aoh, w16 + (size_t)4 * EE * EE,
                                                 bo, emb, res);
    // 6. LN2 -> d_out
    ln_reduce_part<<<lnr_grid, 256>>>(res, part);
    ln_apply4<float><<<(BB * SE / 4 + 255) / 256, 256>>>(
        (const float4*)res, (const float4*)ln2w, (const float4*)ln2b, part, out);
}